// round 14
// baseline (speedup 1.0000x reference)
#include <cuda_runtime.h>
#include <math.h>
#include <stdint.h>

#define DD    20
#define TPB   128
#define GRID  592
#define TROWS 128
#define RAWF  (TROWS*DD)   // 2560 floats
#define HSTR  22

typedef unsigned long long u64;

__device__ __forceinline__ u64 pk(float lo,float hi){u64 r;asm("mov.b64 %0,{%1,%2};":"=l"(r):"f"(lo),"f"(hi));return r;}
__device__ __forceinline__ void upk(u64 v,float&lo,float&hi){asm("mov.b64 {%0,%1},%2;":"=f"(lo),"=f"(hi):"l"(v));}
__device__ __forceinline__ u64 fma2(u64 a,u64 b,u64 c){u64 d;asm("fma.rn.f32x2 %0,%1,%2,%3;":"=l"(d):"l"(a),"l"(b),"l"(c));return d;}
__device__ __forceinline__ uint32_t su(const void*p){return (uint32_t)__cvta_generic_to_shared(p);}
__device__ __forceinline__ void cp16(uint32_t d,const void*s){asm volatile("cp.async.cg.shared.global [%0],[%1],16;"::"r"(d),"l"(s):"memory");}
__device__ __forceinline__ uint32_t tf32u(float x){uint32_t r;asm("cvt.rna.tf32.f32 %0,%1;":"=r"(r):"f"(x));return r;}
__device__ __forceinline__ void mma8(float*d,const uint32_t*a,const uint32_t*b){
  asm volatile("mma.sync.aligned.m16n8k8.row.col.f32.tf32.tf32.f32 {%0,%1,%2,%3},{%4,%5,%6,%7},{%8,%9},{%0,%1,%2,%3};"
   :"+f"(d[0]),"+f"(d[1]),"+f"(d[2]),"+f"(d[3])
   :"r"(a[0]),"r"(a[1]),"r"(a[2]),"r"(a[3]),"r"(b[0]),"r"(b[1]));
}

__device__ double g_pS[1024];
__device__ double g_pQ[1024];
__device__ unsigned int g_ticket = 0;

__global__ void __launch_bounds__(TPB,4)
main_kernel(const float* __restrict__ x, const float* __restrict__ W,
            const float* __restrict__ b,  const float* __restrict__ R,
            float* __restrict__ out, int B) {
    __shared__ __align__(16) float raw[2][RAWF+16];
    __shared__ __align__(16) float hbuf[TROWS*HSTR+8];
    __shared__ float M1s[DD*DD];
    __shared__ __align__(16) float sTf[DD*DD];
    __shared__ __align__(16) u64 swcs2[10], su22[10];
    __shared__ float sc1f[DD], swcsf[DD], su2f[DD], sbf[DD];
    __shared__ double redS[TPB], redQ[TPB];
    __shared__ int sIsLast;

    const int tid=threadIdx.x, lane=tid&31, warp=tid>>5;
    const int gid=lane>>2, tig=lane&3, bid=blockIdx.x;

    // ---- stage W,R in raw[0]; fold ----
    float* stW=raw[0]; float* stR=raw[0]+DD*DD;
    for(int i=tid;i<DD*DD;i+=TPB){ stW[i]=W[i]; stR[i]=R[i]; }
    if(tid<DD) sbf[tid]=b[tid];
    __syncthreads();
    for(int i=tid;i<DD*DD;i+=TPB){
        int k=i/DD, j=i%DD; float m1=0.f,g=0.f;
        #pragma unroll
        for(int m=0;m<DD;m++){ m1=fmaf(stW[m*DD+k],stR[m*DD+j],m1); g=fmaf(stW[m*DD+k],stW[m*DD+j],g); }
        M1s[i]=m1;
        sTf[i]=(j>k)?(2.f*g):((j==k)?g:0.f);
    }
    if(tid<DD){
        float c=1.f,wcs=0.f,u=0.f;
        #pragma unroll
        for(int m=0;m<DD;m++){ c=fmaf(sbf[m],stR[m*DD+tid],c); wcs+=stW[m*DD+tid]; u=fmaf(stW[m*DD+tid],sbf[m],u); }
        sc1f[tid]=c; swcsf[tid]=wcs; su2f[tid]=2.f*u;
    }
    __syncthreads();
    if(tid<10){ swcs2[tid]=pk(swcsf[2*tid],swcsf[2*tid+1]); su22[tid]=pk(su2f[2*tid],su2f[2*tid+1]); }

    // ---- persistent B fragments (M1 hi/lo) + bias regs ----
    uint32_t bhi[3][3][2], blo[3][3][2]; float c1v[6];
    #pragma unroll
    for(int n=0;n<3;n++){
        #pragma unroll
        for(int k=0;k<3;k++){
            #pragma unroll
            for(int j=0;j<2;j++){
                int kk=k*8+tig+j*4, nn=n*8+gid;
                float m=(kk<DD&&nn<DD)?M1s[kk*DD+nn]:0.f;
                uint32_t h=tf32u(m);
                bhi[n][k][j]=h;
                blo[n][k][j]=tf32u(m-__uint_as_float(h));
            }
        }
        #pragma unroll
        for(int j=0;j<2;j++){
            int col=n*8+2*tig+j;
            c1v[n*2+j]=(col<DD)?sc1f[col]:0.f;
        }
    }
    __syncthreads();   // M1s/raw[0] reads done before prologue overwrites

    const int nT=(B+TROWS-1)/TROWS;
    const long long totF=(long long)B*DD;
    auto loadraw=[&](int s,int t){
        long long bf=(long long)t*RAWF;
        #pragma unroll
        for(int i=0;i<5;i++){
            int c=(tid+TPB*i)*4; long long g=bf+c;
            if(g+4<=totF) cp16(su(raw[s]+c), x+g);
            else { float4 v=make_float4(0,0,0,0);
                   if(g<totF)v.x=x[g]; if(g+1<totF)v.y=x[g+1]; if(g+2<totF)v.z=x[g+2]; if(g+3<totF)v.w=x[g+3];
                   *(float4*)(raw[s]+c)=v; }
        }
    };

    if(bid<nT) loadraw(0,bid);
    asm volatile("cp.async.commit_group;":::"memory");

    float sl=0.f, ql=0.f; int lt=0;
    for(int t=bid;t<nT;t+=GRID,lt++){
        int nx=t+GRID;
        if(nx<nT){ loadraw((lt+1)&1,nx); asm volatile("cp.async.commit_group;":::"memory");
                   asm volatile("cp.async.wait_group 1;":::"memory"); }
        else       asm volatile("cp.async.wait_group 0;":::"memory");
        __syncthreads();

        const float* xs=raw[lt&1];
        float d[2][3][4]={};
        #pragma unroll
        for(int k=0;k<3;k++){
            uint32_t ahi[2][4], alo[2][4];
            #pragma unroll
            for(int m=0;m<2;m++){
                int r0=warp*32+m*16;
                float a0=xs[(r0+gid  )*DD + k*8+tig  ];
                float a1=xs[(r0+gid+8)*DD + k*8+tig  ];
                float a2=xs[(r0+gid  )*DD + k*8+tig+4];
                float a3=xs[(r0+gid+8)*DD + k*8+tig+4];
                ahi[m][0]=tf32u(a0); alo[m][0]=tf32u(a0-__uint_as_float(ahi[m][0]));
                ahi[m][1]=tf32u(a1); alo[m][1]=tf32u(a1-__uint_as_float(ahi[m][1]));
                ahi[m][2]=tf32u(a2); alo[m][2]=tf32u(a2-__uint_as_float(ahi[m][2]));
                ahi[m][3]=tf32u(a3); alo[m][3]=tf32u(a3-__uint_as_float(ahi[m][3]));
            }
            #pragma unroll
            for(int m=0;m<2;m++)
            #pragma unroll
            for(int n=0;n<3;n++){
                mma8(d[m][n],ahi[m],bhi[n][k]);
                mma8(d[m][n],alo[m],bhi[n][k]);
                mma8(d[m][n],ahi[m],blo[n][k]);
            }
        }
        // bias + relu + store h (stride-22 rows)
        #pragma unroll
        for(int m=0;m<2;m++){
            int r0=warp*32+m*16+gid;
            #pragma unroll
            for(int n=0;n<3;n++){
                float h0=fmaxf(d[m][n][0]+c1v[n*2  ],0.f);
                float h1=fmaxf(d[m][n][1]+c1v[n*2+1],0.f);
                float h2=fmaxf(d[m][n][2]+c1v[n*2  ],0.f);
                float h3=fmaxf(d[m][n][3]+c1v[n*2+1],0.f);
                if(n<2||tig<3){
                    int cw=n*8+2*tig;
                    *(u64*)(hbuf+(r0  )*HSTR+cw)=pk(h0,h1);
                    *(u64*)(hbuf+(r0+8)*HSTR+cw)=pk(h2,h3);
                }
            }
        }
        __syncthreads();

        // epilogue: one full row per thread, packed f32x2
        const u64* hv=(const u64*)(hbuf+tid*HSTR);
        u64 hp[10];
        #pragma unroll
        for(int j=0;j<10;j++) hp[j]=hv[j];
        u64 s2=0ULL,q2=0ULL;
        #pragma unroll
        for(int j=0;j<10;j++){ s2=fma2(hp[j],swcs2[j],s2); q2=fma2(hp[j],su22[j],q2); }
        float qs=0.f;
        #pragma unroll
        for(int i=0;i<DD;i++){
            u64 y=0ULL; const u64* Tr=(const u64*)(sTf+i*DD);
            #pragma unroll
            for(int kp=i>>1;kp<10;kp++) y=fma2(hp[kp],Tr[kp],y);
            float lo,hi,hl,hh; upk(y,lo,hi); upk(hp[i>>1],hl,hh);
            qs=fmaf((i&1)?hh:hl, lo+hi, qs);
        }
        float lo,hi;
        upk(s2,lo,hi); sl+=lo+hi;
        upk(q2,lo,hi); ql+=lo+hi+qs;
    }

    // ---- block reduce + ticket + last-block finalize ----
    redS[tid]=(double)sl; redQ[tid]=(double)ql;
    __syncthreads();
    for(int s=TPB/2;s>0;s>>=1){ if(tid<s){redS[tid]+=redS[tid+s];redQ[tid]+=redQ[tid+s];} __syncthreads(); }
    if(tid==0){
        g_pS[bid]=redS[0]; g_pQ[bid]=redQ[0];
        __threadfence();
        unsigned int tk=atomicAdd(&g_ticket,1u);
        sIsLast=(tk==(unsigned int)(GRID-1))?1:0;
    }
    __syncthreads();
    if(sIsLast){
        __threadfence();
        double s=0.0,q=0.0;
        for(int i=tid;i<GRID;i+=TPB){ s+=g_pS[i]; q+=g_pQ[i]; }
        redS[tid]=s; redQ[tid]=q;
        __syncthreads();
        for(int st=TPB/2;st>0;st>>=1){ if(tid<st){redS[tid]+=redS[tid+st];redQ[tid]+=redQ[tid+st];} __syncthreads(); }
        if(tid==0){
            float h0[DD];
            #pragma unroll
            for(int j=0;j<DD;j++) h0[j]=fmaxf(sc1f[j],0.f);
            float s0f=0.f,q0f=0.f;
            #pragma unroll
            for(int k=0;k<DD;k++){ s0f=fmaf(h0[k],swcsf[k],s0f); q0f=fmaf(h0[k],su2f[k],q0f); }
            #pragma unroll
            for(int i=0;i<DD;i++){
                float y=0.f;
                #pragma unroll
                for(int k=0;k<DD;k++) y=fmaf(h0[k],sTf[i*DD+k],y);
                q0f=fmaf(h0[i],y,q0f);
            }
            double n_pad=(double)((long long)nT*TROWS-(long long)B);
            double sb=0.0,bb=0.0;
            #pragma unroll
            for(int m=0;m<DD;m++){ sb+=(double)sbf[m]; bb+=(double)sbf[m]*(double)sbf[m]; }
            double S=redS[0]-n_pad*(double)s0f+(double)B*sb;
            double Q=redQ[0]-n_pad*(double)q0f+(double)B*bb;
            float n=(float)sqrt(Q);
            int k=0;
            while(n>1.0f&&k<300){ n*=0.5f; k++; }
            float mult=(n<0.8f)?10.0f:1.0f;
            out[0]=(float)(S*ldexp(1.0,-k)*(double)mult);
            g_ticket=0;
        }
    }
}

extern "C" void kernel_launch(void* const* d_in, const int* in_sizes, int n_in,
                              void* d_out, int out_size) {
    const float* x=(const float*)d_in[0];
    const float* W=(const float*)d_in[1];
    const float* b=(const float*)d_in[2];
    const float* R=(const float*)d_in[3];
    int B=in_sizes[0]/DD;
    main_kernel<<<GRID,TPB>>>(x,W,b,R,(float*)d_out,B);
}

// round 15
// speedup vs baseline: 1.0436x; 1.0436x over previous
#include <cuda_runtime.h>
#include <math.h>
#include <stdint.h>

#define DD    20
#define TPB   128
#define GRID  592
#define TROWS 128
#define RAWF  (TROWS*DD)
#define HSTR  24

typedef unsigned long long u64;

__device__ __forceinline__ u64 pk(float lo,float hi){u64 r;asm("mov.b64 %0,{%1,%2};":"=l"(r):"f"(lo),"f"(hi));return r;}
__device__ __forceinline__ uint32_t su(const void*p){return (uint32_t)__cvta_generic_to_shared(p);}
__device__ __forceinline__ void cp16(uint32_t d,const void*s){asm volatile("cp.async.cg.shared.global [%0],[%1],16;"::"r"(d),"l"(s):"memory");}
__device__ __forceinline__ uint32_t tf32u(float x){uint32_t r;asm("cvt.rna.tf32.f32 %0,%1;":"=r"(r):"f"(x));return r;}
__device__ __forceinline__ void mma8(float*d,const uint32_t*a,const uint32_t*b){
  asm volatile("mma.sync.aligned.m16n8k8.row.col.f32.tf32.tf32.f32 {%0,%1,%2,%3},{%4,%5,%6,%7},{%8,%9},{%0,%1,%2,%3};"
   :"+f"(d[0]),"+f"(d[1]),"+f"(d[2]),"+f"(d[3])
   :"r"(a[0]),"r"(a[1]),"r"(a[2]),"r"(a[3]),"r"(b[0]),"r"(b[1]));
}

__device__ double g_pS[1024];
__device__ double g_pQ[1024];
__device__ unsigned int g_ticket = 0;

__global__ void __launch_bounds__(TPB,4)
main_kernel(const float* __restrict__ x, const float* __restrict__ W,
            const float* __restrict__ b,  const float* __restrict__ R,
            float* __restrict__ out, int B) {
    __shared__ __align__(16) float raw[2][RAWF+16];
    __shared__ __align__(16) float hbuf[TROWS*HSTR];
    __shared__ float M1s[DD*DD];
    __shared__ __align__(16) float sGf[DD*DD];       // plain G = W^T W
    __shared__ float sc1f[24], swcsf[24], su2f[24], sbf[DD];
    __shared__ double redS[TPB], redQ[TPB];
    __shared__ int sIsLast;

    const int tid=threadIdx.x, lane=tid&31, warp=tid>>5;
    const int gid=lane>>2, tig=lane&3, bid=blockIdx.x;

    // ---- stage + fold ----
    float* stW=raw[0]; float* stR=raw[0]+DD*DD;
    for(int i=tid;i<DD*DD;i+=TPB){ stW[i]=W[i]; stR[i]=R[i]; }
    if(tid<DD) sbf[tid]=b[tid];
    __syncthreads();
    for(int i=tid;i<DD*DD;i+=TPB){
        int k=i/DD, j=i%DD; float m1=0.f,g=0.f;
        #pragma unroll
        for(int m=0;m<DD;m++){ m1=fmaf(stW[m*DD+k],stR[m*DD+j],m1); g=fmaf(stW[m*DD+k],stW[m*DD+j],g); }
        M1s[i]=m1; sGf[i]=g;
    }
    if(tid<DD){
        float c=1.f,wcs=0.f,u=0.f;
        #pragma unroll
        for(int m=0;m<DD;m++){ c=fmaf(sbf[m],stR[m*DD+tid],c); wcs+=stW[m*DD+tid]; u=fmaf(stW[m*DD+tid],sbf[m],u); }
        sc1f[tid]=c; swcsf[tid]=wcs; su2f[tid]=2.f*u;
    } else if(tid<24){ sc1f[tid]=0.f; swcsf[tid]=0.f; su2f[tid]=0.f; }
    __syncthreads();

    // ---- persistent M1 B-fragments (hi/lo) + bias cols ----
    uint32_t bhi[3][3][2], blo[3][3][2]; float c1v[6];
    #pragma unroll
    for(int n=0;n<3;n++){
        #pragma unroll
        for(int k=0;k<3;k++)
        #pragma unroll
        for(int j=0;j<2;j++){
            int kk=k*8+tig+j*4, nn=n*8+gid;
            float m=(kk<DD&&nn<DD)?M1s[kk*DD+nn]:0.f;
            uint32_t h=tf32u(m);
            bhi[n][k][j]=h; blo[n][k][j]=tf32u(m-__uint_as_float(h));
        }
        #pragma unroll
        for(int j=0;j<2;j++) c1v[n*2+j]=sc1f[n*8+2*tig+j];
    }
    __syncthreads();
    if(tid<16){ raw[0][RAWF+tid]=0.f; raw[1][RAWF+tid]=0.f; }  // pad: kill NaN risk
    __syncthreads();

    const int nT=(B+TROWS-1)/TROWS;
    const long long totF=(long long)B*DD;
    auto loadraw=[&](int s,int t){
        long long bf=(long long)t*RAWF;
        #pragma unroll
        for(int i=0;i<5;i++){
            int c=(tid+TPB*i)*4; long long g=bf+c;
            if(g+4<=totF) cp16(su(raw[s]+c), x+g);
            else { float4 v=make_float4(0,0,0,0);
                   if(g<totF)v.x=x[g]; if(g+1<totF)v.y=x[g+1]; if(g+2<totF)v.z=x[g+2]; if(g+3<totF)v.w=x[g+3];
                   *(float4*)(raw[s]+c)=v; }
        }
    };

    if(bid<nT) loadraw(0,bid);
    asm volatile("cp.async.commit_group;":::"memory");

    float sl=0.f, ql=0.f;
    float gm[2][3][4]={};          // persistent Gram accumulators
    int lt=0;
    for(int t=bid;t<nT;t+=GRID,lt++){
        int nx=t+GRID;
        if(nx<nT){ loadraw((lt+1)&1,nx); asm volatile("cp.async.commit_group;":::"memory");
                   asm volatile("cp.async.wait_group 1;":::"memory"); }
        else       asm volatile("cp.async.wait_group 0;":::"memory");
        __syncthreads();

        // ---- MMA1: h_pre = x @ M1, 2-pass (xhi only) ----
        const float* xs=raw[lt&1];
        float d[2][3][4]={};
        #pragma unroll
        for(int k=0;k<3;k++){
            uint32_t ah[2][4];
            #pragma unroll
            for(int m=0;m<2;m++){
                int r0=warp*32+m*16;
                ah[m][0]=tf32u(xs[(r0+gid  )*DD + k*8+tig  ]);
                ah[m][1]=tf32u(xs[(r0+gid+8)*DD + k*8+tig  ]);
                ah[m][2]=tf32u(xs[(r0+gid  )*DD + k*8+tig+4]);
                ah[m][3]=tf32u(xs[(r0+gid+8)*DD + k*8+tig+4]);
            }
            #pragma unroll
            for(int m=0;m<2;m++)
            #pragma unroll
            for(int n=0;n<3;n++){
                mma8(d[m][n],ah[m],bhi[n][k]);
                mma8(d[m][n],ah[m],blo[n][k]);
            }
        }
        // ---- bias+relu, S/Qlin dots, store h ----
        #pragma unroll
        for(int m=0;m<2;m++){
            int r0=warp*32+m*16+gid;
            #pragma unroll
            for(int n=0;n<3;n++){
                float h0=fmaxf(d[m][n][0]+c1v[n*2  ],0.f);
                float h1=fmaxf(d[m][n][1]+c1v[n*2+1],0.f);
                float h2=fmaxf(d[m][n][2]+c1v[n*2  ],0.f);
                float h3=fmaxf(d[m][n][3]+c1v[n*2+1],0.f);
                int c0=n*8+2*tig;
                float w0=swcsf[c0], w1=swcsf[c0+1], u0=su2f[c0], u1=su2f[c0+1];
                sl=fmaf(h0+h2,w0,sl); sl=fmaf(h1+h3,w1,sl);
                ql=fmaf(h0+h2,u0,ql); ql=fmaf(h1+h3,u1,ql);
                *(u64*)(hbuf+(r0  )*HSTR+c0)=pk(h0,h1);
                *(u64*)(hbuf+(r0+8)*HSTR+c0)=pk(h2,h3);
            }
        }
        __syncthreads();

        // ---- Gram MMA: gm += Hhi^T Hhi + Hhi^T (2*Hlo)  (own 32 rows as k) ----
        #pragma unroll
        for(int kb=0;kb<4;kb++){
            const float* hr0=hbuf+(warp*32+kb*8+tig  )*HSTR;
            const float* hr1=hbuf+(warp*32+kb*8+tig+4)*HSTR;
            float u0=hr0[gid], u1=hr0[gid+8], u2e=hr0[gid+16];
            float v0=hr1[gid], v1=hr1[gid+8], v2e=hr1[gid+16];
            uint32_t u0h=tf32u(u0),u1h=tf32u(u1),u2h=tf32u(u2e);
            uint32_t v0h=tf32u(v0),v1h=tf32u(v1),v2h=tf32u(v2e);
            float l; uint32_t u0l,u1l,u2l,v0l,v1l,v2l;
            l=u0-__uint_as_float(u0h); u0l=tf32u(l+l);
            l=u1-__uint_as_float(u1h); u1l=tf32u(l+l);
            l=u2e-__uint_as_float(u2h); u2l=tf32u(l+l);
            l=v0-__uint_as_float(v0h); v0l=tf32u(l+l);
            l=v1-__uint_as_float(v1h); v1l=tf32u(l+l);
            l=v2e-__uint_as_float(v2h); v2l=tf32u(l+l);
            uint32_t a0[4]={u0h,u1h,v0h,v1h};
            uint32_t a1[4]={u2h,0u ,v2h,0u };
            uint32_t bh0[2]={u0h,v0h}, bh1[2]={u1h,v1h}, bh2[2]={u2h,v2h};
            uint32_t bl0[2]={u0l,v0l}, bl1[2]={u1l,v1l}, bl2[2]={u2l,v2l};
            mma8(gm[0][0],a0,bh0); mma8(gm[0][0],a0,bl0);
            mma8(gm[0][1],a0,bh1); mma8(gm[0][1],a0,bl1);
            mma8(gm[0][2],a0,bh2); mma8(gm[0][2],a0,bl2);
            mma8(gm[1][0],a1,bh0); mma8(gm[1][0],a1,bl0);
            mma8(gm[1][1],a1,bh1); mma8(gm[1][1],a1,bl1);
            mma8(gm[1][2],a1,bh2); mma8(gm[1][2],a1,bl2);
        }
    }

    // ---- contract Gram fragments with G (once) ----
    #pragma unroll
    for(int mb=0;mb<2;mb++)
    #pragma unroll
    for(int nb=0;nb<3;nb++)
    #pragma unroll
    for(int e=0;e<4;e++){
        int r=mb*16+gid+((e>>1)?8:0);
        int c=nb*8+2*tig+(e&1);
        if(r<DD&&c<DD) ql=fmaf(gm[mb][nb][e],sGf[r*DD+c],ql);
    }

    // ---- block reduce + ticket + last-block finalize ----
    redS[tid]=(double)sl; redQ[tid]=(double)ql;
    __syncthreads();
    for(int s=TPB/2;s>0;s>>=1){ if(tid<s){redS[tid]+=redS[tid+s];redQ[tid]+=redQ[tid+s];} __syncthreads(); }
    if(tid==0){
        g_pS[bid]=redS[0]; g_pQ[bid]=redQ[0];
        __threadfence();
        unsigned int tk=atomicAdd(&g_ticket,1u);
        sIsLast=(tk==(unsigned int)(GRID-1))?1:0;
    }
    __syncthreads();
    if(sIsLast){
        __threadfence();
        double s=0.0,q=0.0;
        for(int i=tid;i<GRID;i+=TPB){ s+=g_pS[i]; q+=g_pQ[i]; }
        redS[tid]=s; redQ[tid]=q;
        __syncthreads();
        for(int st=TPB/2;st>0;st>>=1){ if(tid<st){redS[tid]+=redS[tid+st];redQ[tid]+=redQ[tid+st];} __syncthreads(); }
        if(tid==0){
            float h0[DD];
            #pragma unroll
            for(int j=0;j<DD;j++) h0[j]=fmaxf(sc1f[j],0.f);
            float s0f=0.f,q0f=0.f;
            #pragma unroll
            for(int k=0;k<DD;k++){ s0f=fmaf(h0[k],swcsf[k],s0f); q0f=fmaf(h0[k],su2f[k],q0f); }
            #pragma unroll
            for(int i=0;i<DD;i++){
                float y=0.f;
                #pragma unroll
                for(int k=0;k<DD;k++) y=fmaf(h0[k],sGf[i*DD+k],y);
                q0f=fmaf(h0[i],y,q0f);
            }
            double n_pad=(double)((long long)nT*TROWS-(long long)B);
            double sb=0.0,bb=0.0;
            #pragma unroll
            for(int m=0;m<DD;m++){ sb+=(double)sbf[m]; bb+=(double)sbf[m]*(double)sbf[m]; }
            double S=redS[0]-n_pad*(double)s0f+(double)B*sb;
            double Q=redQ[0]-n_pad*(double)q0f+(double)B*bb;
            float n=(float)sqrt(Q);
            int k=0;
            while(n>1.0f&&k<300){ n*=0.5f; k++; }
            float mult=(n<0.8f)?10.0f:1.0f;
            out[0]=(float)(S*ldexp(1.0,-k)*(double)mult);
            g_ticket=0;
        }
    }
}

extern "C" void kernel_launch(void* const* d_in, const int* in_sizes, int n_in,
                              void* d_out, int out_size) {
    const float* x=(const float*)d_in[0];
    const float* W=(const float*)d_in[1];
    const float* b=(const float*)d_in[2];
    const float* R=(const float*)d_in[3];
    int B=in_sizes[0]/DD;
    main_kernel<<<GRID,TPB>>>(x,W,b,R,(float*)d_out,B);
}

// round 16
// speedup vs baseline: 1.3832x; 1.3254x over previous
#include <cuda_runtime.h>
#include <math.h>
#include <stdint.h>

#define DD    20
#define TPB   128
#define GRID  592
#define TROWS 128
#define RAWF  (TROWS*DD)
#define HSTR  24

typedef unsigned long long u64;

__device__ __forceinline__ u64 pk(float lo,float hi){u64 r;asm("mov.b64 %0,{%1,%2};":"=l"(r):"f"(lo),"f"(hi));return r;}
__device__ __forceinline__ uint32_t su(const void*p){return (uint32_t)__cvta_generic_to_shared(p);}
__device__ __forceinline__ void cp16(uint32_t d,const void*s){asm volatile("cp.async.cg.shared.global [%0],[%1],16;"::"r"(d),"l"(s):"memory");}
__device__ __forceinline__ uint32_t tf32u(float x){uint32_t r;asm("cvt.rna.tf32.f32 %0,%1;":"=r"(r):"f"(x));return r;}
__device__ __forceinline__ void mma8(float*d,const uint32_t*a,const uint32_t*b){
  asm volatile("mma.sync.aligned.m16n8k8.row.col.f32.tf32.tf32.f32 {%0,%1,%2,%3},{%4,%5,%6,%7},{%8,%9},{%0,%1,%2,%3};"
   :"+f"(d[0]),"+f"(d[1]),"+f"(d[2]),"+f"(d[3])
   :"r"(a[0]),"r"(a[1]),"r"(a[2]),"r"(a[3]),"r"(b[0]),"r"(b[1]));
}

__device__ double g_pS[1024];
__device__ double g_pQ[1024];
__device__ unsigned int g_ticket = 0;

__global__ void __launch_bounds__(TPB,4)
main_kernel(const float* __restrict__ x, const float* __restrict__ W,
            const float* __restrict__ b,  const float* __restrict__ R,
            float* __restrict__ out, int B) {
    __shared__ __align__(16) float raw[2][RAWF+16];
    __shared__ __align__(16) float hbuf[TROWS*HSTR];
    __shared__ float M1s[DD*DD];
    __shared__ __align__(16) float sGf[DD*DD];
    __shared__ float sc1f[24], swcsf[24], su2f[24], sbf[DD];
    __shared__ double redS[TPB], redQ[TPB];
    __shared__ int sIsLast;

    const int tid=threadIdx.x, lane=tid&31, warp=tid>>5;
    const int gid=lane>>2, tig=lane&3, bid=blockIdx.x;

    // ---- stage + fold ----
    float* stW=raw[0]; float* stR=raw[0]+DD*DD;
    for(int i=tid;i<DD*DD;i+=TPB){ stW[i]=W[i]; stR[i]=R[i]; }
    if(tid<DD) sbf[tid]=b[tid];
    __syncthreads();
    for(int i=tid;i<DD*DD;i+=TPB){
        int k=i/DD, j=i%DD; float m1=0.f,g=0.f;
        #pragma unroll
        for(int m=0;m<DD;m++){ m1=fmaf(stW[m*DD+k],stR[m*DD+j],m1); g=fmaf(stW[m*DD+k],stW[m*DD+j],g); }
        M1s[i]=m1; sGf[i]=g;
    }
    if(tid<DD){
        float c=1.f,wcs=0.f,u=0.f;
        #pragma unroll
        for(int m=0;m<DD;m++){ c=fmaf(sbf[m],stR[m*DD+tid],c); wcs+=stW[m*DD+tid]; u=fmaf(stW[m*DD+tid],sbf[m],u); }
        sc1f[tid]=c; swcsf[tid]=wcs; su2f[tid]=2.f*u;
    } else if(tid<24){ sc1f[tid]=0.f; swcsf[tid]=0.f; su2f[tid]=0.f; }
    __syncthreads();

    // ---- persistent M1 B-fragments (hi/lo) + bias cols ----
    uint32_t bhi[3][3][2], blo[3][3][2]; float c1v[6];
    #pragma unroll
    for(int n=0;n<3;n++){
        #pragma unroll
        for(int k=0;k<3;k++)
        #pragma unroll
        for(int j=0;j<2;j++){
            int kk=k*8+tig+j*4, nn=n*8+gid;
            float m=(kk<DD&&nn<DD)?M1s[kk*DD+nn]:0.f;
            uint32_t h=tf32u(m);
            bhi[n][k][j]=h; blo[n][k][j]=tf32u(m-__uint_as_float(h));
        }
        #pragma unroll
        for(int j=0;j<2;j++) c1v[n*2+j]=sc1f[n*8+2*tig+j];
    }
    __syncthreads();
    if(tid<16){ raw[0][RAWF+tid]=0.f; raw[1][RAWF+tid]=0.f; }  // A-read overrun pad
    __syncthreads();

    const int nT=(B+TROWS-1)/TROWS;
    const long long totF=(long long)B*DD;
    auto loadraw=[&](int s,int t){
        long long bf=(long long)t*RAWF;
        #pragma unroll
        for(int i=0;i<5;i++){
            int c=(tid+TPB*i)*4; long long g=bf+c;
            if(g+4<=totF) cp16(su(raw[s]+c), x+g);
            else { float4 v=make_float4(0,0,0,0);
                   if(g<totF)v.x=x[g]; if(g+1<totF)v.y=x[g+1]; if(g+2<totF)v.z=x[g+2]; if(g+3<totF)v.w=x[g+3];
                   *(float4*)(raw[s]+c)=v; }
        }
    };

    if(bid<nT) loadraw(0,bid);
    asm volatile("cp.async.commit_group;":::"memory");

    float sl=0.f, ql=0.f;
    float gm[4][4]={};   // Gram blocks: (0,0),(0,1),(0,2)x2,(1,2)
    int lt=0;
    for(int t=bid;t<nT;t+=GRID,lt++){
        int nx=t+GRID;
        if(nx<nT){ loadraw((lt+1)&1,nx); asm volatile("cp.async.commit_group;":::"memory");
                   asm volatile("cp.async.wait_group 1;":::"memory"); }
        else       asm volatile("cp.async.wait_group 0;":::"memory");
        __syncthreads();

        // ---- MMA1: h_pre = x @ M1 (2-pass err-compensated) ----
        const float* xs=raw[lt&1];
        float d[2][3][4]={};
        #pragma unroll
        for(int k=0;k<3;k++){
            uint32_t ah[2][4];
            #pragma unroll
            for(int m=0;m<2;m++){
                int r0=warp*32+m*16;
                ah[m][0]=tf32u(xs[(r0+gid  )*DD + k*8+tig  ]);
                ah[m][1]=tf32u(xs[(r0+gid+8)*DD + k*8+tig  ]);
                ah[m][2]=tf32u(xs[(r0+gid  )*DD + k*8+tig+4]);
                ah[m][3]=tf32u(xs[(r0+gid+8)*DD + k*8+tig+4]);
            }
            #pragma unroll
            for(int m=0;m<2;m++)
            #pragma unroll
            for(int n=0;n<3;n++){
                mma8(d[m][n],ah[m],bhi[n][k]);
                mma8(d[m][n],ah[m],blo[n][k]);
            }
        }
        // ---- bias+relu, S/Qlin dots (fp32 h), store tf32-rounded h ----
        #pragma unroll
        for(int m=0;m<2;m++){
            int r0=warp*32+m*16+gid;
            #pragma unroll
            for(int n=0;n<3;n++){
                float h0=fmaxf(d[m][n][0]+c1v[n*2  ],0.f);
                float h1=fmaxf(d[m][n][1]+c1v[n*2+1],0.f);
                float h2=fmaxf(d[m][n][2]+c1v[n*2  ],0.f);
                float h3=fmaxf(d[m][n][3]+c1v[n*2+1],0.f);
                int c0=n*8+2*tig;
                float w0=swcsf[c0], w1=swcsf[c0+1], u0=su2f[c0], u1=su2f[c0+1];
                sl=fmaf(h0+h2,w0,sl); sl=fmaf(h1+h3,w1,sl);
                ql=fmaf(h0+h2,u0,ql); ql=fmaf(h1+h3,u1,ql);
                *(u64*)(hbuf+(r0  )*HSTR+c0)=pk(__uint_as_float(tf32u(h0)),__uint_as_float(tf32u(h1)));
                *(u64*)(hbuf+(r0+8)*HSTR+c0)=pk(__uint_as_float(tf32u(h2)),__uint_as_float(tf32u(h3)));
            }
        }
        __syncthreads();

        // ---- Gram MMA, single-pass, symmetry-halved ----
        #pragma unroll
        for(int kb=0;kb<4;kb++){
            const float* hr0=hbuf+(warp*32+kb*8+tig  )*HSTR;
            const float* hr1=hbuf+(warp*32+kb*8+tig+4)*HSTR;
            uint32_t u0=__float_as_uint(hr0[gid]);
            uint32_t u1=__float_as_uint(hr0[gid+8]);
            uint32_t u2=__float_as_uint(hr0[gid+16]);
            uint32_t v0=__float_as_uint(hr1[gid]);
            uint32_t v1=__float_as_uint(hr1[gid+8]);
            uint32_t v2=__float_as_uint(hr1[gid+16]);
            uint32_t a0[4]={u0,u1,v0,v1};
            uint32_t a1[4]={u2,0u,v2,0u};
            uint32_t b0[2]={u0,v0}, b1[2]={u1,v1}, b2[2]={u2,v2};
            mma8(gm[0],a0,b0);
            mma8(gm[1],a0,b1);
            mma8(gm[2],a0,b2);
            mma8(gm[3],a1,b2);
        }
    }

    // ---- contract Gram fragments with G (symmetry weights) ----
    {
        const int mb[4]={0,0,0,1}, nb[4]={0,1,2,2};
        const float wt[4]={1.f,1.f,2.f,1.f};
        #pragma unroll
        for(int bi=0;bi<4;bi++)
        #pragma unroll
        for(int e=0;e<4;e++){
            int r=mb[bi]*16+gid+((e>>1)?8:0);
            int c=nb[bi]*8+2*tig+(e&1);
            if(r<DD&&c<DD) ql=fmaf(gm[bi][e]*wt[bi], sGf[r*DD+c], ql);
        }
    }

    // ---- block reduce + ticket + last-block finalize ----
    redS[tid]=(double)sl; redQ[tid]=(double)ql;
    __syncthreads();
    for(int s=TPB/2;s>0;s>>=1){ if(tid<s){redS[tid]+=redS[tid+s];redQ[tid]+=redQ[tid+s];} __syncthreads(); }
    if(tid==0){
        g_pS[bid]=redS[0]; g_pQ[bid]=redQ[0];
        __threadfence();
        unsigned int tk=atomicAdd(&g_ticket,1u);
        sIsLast=(tk==(unsigned int)(GRID-1))?1:0;
    }
    __syncthreads();
    if(sIsLast){
        __threadfence();
        double s=0.0,q=0.0;
        for(int i=tid;i<GRID;i+=TPB){ s+=g_pS[i]; q+=g_pQ[i]; }
        redS[tid]=s; redQ[tid]=q;
        __syncthreads();
        for(int st=TPB/2;st>0;st>>=1){ if(tid<st){redS[tid]+=redS[tid+st];redQ[tid]+=redQ[tid+st];} __syncthreads(); }
        if(tid==0){
            float h0[DD];
            #pragma unroll
            for(int j=0;j<DD;j++) h0[j]=fmaxf(sc1f[j],0.f);
            float s0f=0.f,q0f=0.f;
            #pragma unroll
            for(int k=0;k<DD;k++){ s0f=fmaf(h0[k],swcsf[k],s0f); q0f=fmaf(h0[k],su2f[k],q0f); }
            #pragma unroll
            for(int i=0;i<DD;i++){
                float y=0.f;
                #pragma unroll
                for(int k=0;k<DD;k++) y=fmaf(h0[k],sGf[i*DD+k],y);
                q0f=fmaf(h0[i],y,q0f);
            }
            double n_pad=(double)((long long)nT*TROWS-(long long)B);
            double sb=0.0,bb=0.0;
            #pragma unroll
            for(int m=0;m<DD;m++){ sb+=(double)sbf[m]; bb+=(double)sbf[m]*(double)sbf[m]; }
            double S=redS[0]-n_pad*(double)s0f+(double)B*sb;
            double Q=redQ[0]-n_pad*(double)q0f+(double)B*bb;
            float n=(float)sqrt(Q);
            int k=0;
            while(n>1.0f&&k<300){ n*=0.5f; k++; }
            float mult=(n<0.8f)?10.0f:1.0f;
            out[0]=(float)(S*ldexp(1.0,-k)*(double)mult);
            g_ticket=0;
        }
    }
}

extern "C" void kernel_launch(void* const* d_in, const int* in_sizes, int n_in,
                              void* d_out, int out_size) {
    const float* x=(const float*)d_in[0];
    const float* W=(const float*)d_in[1];
    const float* b=(const float*)d_in[2];
    const float* R=(const float*)d_in[3];
    int B=in_sizes[0]/DD;
    main_kernel<<<GRID,TPB>>>(x,W,b,R,(float*)d_out,B);
}

// round 17
// speedup vs baseline: 1.4287x; 1.0329x over previous
#include <cuda_runtime.h>
#include <math.h>
#include <stdint.h>

#define DD    20
#define TPB   128
#define GRID  592
#define TROWS 128
#define RAWF  (TROWS*DD)
#define HSTR  24

typedef unsigned long long u64;

__device__ __forceinline__ u64 pk(float lo,float hi){u64 r;asm("mov.b64 %0,{%1,%2};":"=l"(r):"f"(lo),"f"(hi));return r;}
__device__ __forceinline__ uint32_t su(const void*p){return (uint32_t)__cvta_generic_to_shared(p);}
__device__ __forceinline__ void cp16(uint32_t d,const void*s){asm volatile("cp.async.cg.shared.global [%0],[%1],16;"::"r"(d),"l"(s):"memory");}
__device__ __forceinline__ uint32_t tf32u(float x){uint32_t r;asm("cvt.rna.tf32.f32 %0,%1;":"=r"(r):"f"(x));return r;}
__device__ __forceinline__ float tf32f(float x){return __uint_as_float(tf32u(x));}
__device__ __forceinline__ void mma8(float*d,const uint32_t*a,const uint32_t*b){
  asm volatile("mma.sync.aligned.m16n8k8.row.col.f32.tf32.tf32.f32 {%0,%1,%2,%3},{%4,%5,%6,%7},{%8,%9},{%0,%1,%2,%3};"
   :"+f"(d[0]),"+f"(d[1]),"+f"(d[2]),"+f"(d[3])
   :"r"(a[0]),"r"(a[1]),"r"(a[2]),"r"(a[3]),"r"(b[0]),"r"(b[1]));
}

__device__ double g_pS[1024];
__device__ double g_pQ[1024];
__device__ unsigned int g_ticket = 0;

__global__ void __launch_bounds__(TPB,4)
main_kernel(const float* __restrict__ x, const float* __restrict__ W,
            const float* __restrict__ b,  const float* __restrict__ R,
            float* __restrict__ out, int B) {
    __shared__ __align__(16) float raw[2][RAWF+16];
    __shared__ __align__(16) float hbuf[TROWS*HSTR];
    __shared__ float M1s[DD*DD];
    __shared__ __align__(16) float sGf[DD*DD];
    __shared__ float sc1f[24], swcsf[24], su2f[24], sbf[DD];
    __shared__ double redS[TPB], redQ[TPB];
    __shared__ int sIsLast;

    const int tid=threadIdx.x, lane=tid&31, warp=tid>>5;
    const int gid=lane>>2, tig=lane&3, bid=blockIdx.x;

    // ---- stage + fold ----
    float* stW=raw[0]; float* stR=raw[0]+DD*DD;
    for(int i=tid;i<DD*DD;i+=TPB){ stW[i]=W[i]; stR[i]=R[i]; }
    if(tid<DD) sbf[tid]=b[tid];
    __syncthreads();
    for(int i=tid;i<DD*DD;i+=TPB){
        int k=i/DD, j=i%DD; float m1=0.f,g=0.f;
        #pragma unroll
        for(int m=0;m<DD;m++){ m1=fmaf(stW[m*DD+k],stR[m*DD+j],m1); g=fmaf(stW[m*DD+k],stW[m*DD+j],g); }
        M1s[i]=m1; sGf[i]=g;
    }
    if(tid<DD){
        float c=1.f,wcs=0.f,u=0.f;
        #pragma unroll
        for(int m=0;m<DD;m++){ c=fmaf(sbf[m],stR[m*DD+tid],c); wcs+=stW[m*DD+tid]; u=fmaf(stW[m*DD+tid],sbf[m],u); }
        sc1f[tid]=c; swcsf[tid]=wcs; su2f[tid]=2.f*u;
    } else if(tid<24){ sc1f[tid]=0.f; swcsf[tid]=0.f; su2f[tid]=0.f; }
    __syncthreads();

    // ---- persistent M1 B-fragments (hi/lo) + bias cols ----
    uint32_t bhi[3][3][2], blo[3][3][2]; float c1v[6];
    #pragma unroll
    for(int n=0;n<3;n++){
        #pragma unroll
        for(int k=0;k<3;k++)
        #pragma unroll
        for(int j=0;j<2;j++){
            int kk=k*8+tig+j*4, nn=n*8+gid;
            float m=(kk<DD&&nn<DD)?M1s[kk*DD+nn]:0.f;
            uint32_t h=tf32u(m);
            bhi[n][k][j]=h; blo[n][k][j]=tf32u(m-__uint_as_float(h));
        }
        #pragma unroll
        for(int j=0;j<2;j++) c1v[n*2+j]=sc1f[n*8+2*tig+j];
    }
    __syncthreads();
    if(tid<16){ raw[0][RAWF+tid]=0.f; raw[1][RAWF+tid]=0.f; }
    __syncthreads();

    const int nT=(B+TROWS-1)/TROWS;
    const long long totF=(long long)B*DD;
    auto loadraw=[&](int s,int t){
        if(t>=nT) return;
        long long bf=(long long)t*RAWF;
        #pragma unroll
        for(int i=0;i<5;i++){
            int c=(tid+TPB*i)*4; long long g=bf+c;
            if(g+4<=totF) cp16(su(raw[s]+c), x+g);
            else { float4 v=make_float4(0,0,0,0);
                   if(g<totF)v.x=x[g]; if(g+1<totF)v.y=x[g+1]; if(g+2<totF)v.z=x[g+2]; if(g+3<totF)v.w=x[g+3];
                   *(float4*)(raw[s]+c)=v; }
        }
    };

    loadraw(0,bid);
    asm volatile("cp.async.commit_group;":::"memory");
    loadraw(1,bid+GRID);
    asm volatile("cp.async.commit_group;":::"memory");

    float gm[4][4]={};   // Gram blocks (0,0),(0,1),(0,2)x2,(1,2); col 20 carries colsum

    // per-thread bases
    const int rowA = warp*32+gid;
    float* hst0 = hbuf + (warp*32+gid)*HSTR;   // store rows r0, r0+8 via offsets

    auto process=[&](const float* xs, int slot, int pre){
        // ---- MMA1: h_pre = x @ M1 (2-pass err-compensated) ----
        const float* xp0 = xs + rowA*DD + tig;        // rows gid / gid+8, k offsets immediate
        float d[2][3][4]={};
        #pragma unroll
        for(int k=0;k<3;k++){
            uint32_t ah[2][4];
            #pragma unroll
            for(int m=0;m<2;m++){
                const float* p = xp0 + m*16*DD;
                ah[m][0]=tf32u(p[k*8]);
                ah[m][1]=tf32u(p[8*DD + k*8]);
                ah[m][2]=tf32u(p[k*8+4]);
                ah[m][3]=tf32u(p[8*DD + k*8+4]);
            }
            #pragma unroll
            for(int m=0;m<2;m++)
            #pragma unroll
            for(int n=0;n<3;n++){
                mma8(d[m][n],ah[m],bhi[n][k]);
                mma8(d[m][n],ah[m],blo[n][k]);
            }
        }
        // ---- bias+relu, store tf32-rounded h (col 20 forced to 1.0) ----
        #pragma unroll
        for(int m=0;m<2;m++){
            float* hs = hst0 + m*16*HSTR;
            #pragma unroll
            for(int n=0;n<3;n++){
                float h0=tf32f(fmaxf(d[m][n][0]+c1v[n*2  ],0.f));
                float h1=tf32f(fmaxf(d[m][n][1]+c1v[n*2+1],0.f));
                float h2=tf32f(fmaxf(d[m][n][2]+c1v[n*2  ],0.f));
                float h3=tf32f(fmaxf(d[m][n][3]+c1v[n*2+1],0.f));
                if(n==2&&tig==2){ h0=1.f; h1=0.f; h2=1.f; h3=0.f; }   // ones column 20
                int c0=n*8+2*tig;
                *(u64*)(hs+c0)        =pk(h0,h1);
                *(u64*)(hs+8*HSTR+c0) =pk(h2,h3);
            }
        }
        __syncthreads();                      // raw reads done too -> safe to refill
        loadraw(slot,pre);                    // overlap next DRAM load with Gram
        asm volatile("cp.async.commit_group;":::"memory");

        // ---- Gram MMA, single-pass, symmetry-halved ----
        #pragma unroll
        for(int kb=0;kb<4;kb++){
            const float* hr0=hbuf+(warp*32+kb*8+tig  )*HSTR;
            const float* hr1=hbuf+(warp*32+kb*8+tig+4)*HSTR;
            uint32_t u0=__float_as_uint(hr0[gid]);
            uint32_t u1=__float_as_uint(hr0[gid+8]);
            uint32_t u2=__float_as_uint(hr0[gid+16]);
            uint32_t v0=__float_as_uint(hr1[gid]);
            uint32_t v1=__float_as_uint(hr1[gid+8]);
            uint32_t v2=__float_as_uint(hr1[gid+16]);
            uint32_t a0[4]={u0,u1,v0,v1};
            uint32_t a1[4]={u2,0u,v2,0u};
            uint32_t b0[2]={u0,v0}, b1[2]={u1,v1}, b2[2]={u2,v2};
            mma8(gm[0],a0,b0);
            mma8(gm[1],a0,b1);
            mma8(gm[2],a0,b2);
            mma8(gm[3],a1,b2);
        }
    };

    // ---- main loop: 2x unrolled over double buffer ----
    for(int t=bid; t<nT; ){
        asm volatile("cp.async.wait_group 1;":::"memory");
        __syncthreads();
        process(raw[0], 0, t+2*GRID);
        t+=GRID; if(t>=nT) break;
        asm volatile("cp.async.wait_group 1;":::"memory");
        __syncthreads();
        process(raw[1], 1, t+2*GRID);
        t+=GRID;
    }

    // ---- contract Gram fragments: quadratic (G), S & Qlin (col 20) ----
    float sl=0.f, ql=0.f;
    {
        const int mb4[4]={0,0,0,1}, nb4[4]={0,1,2,2};
        const float wtG[4]={1.f,1.f,2.f,1.f};
        #pragma unroll
        for(int bi=0;bi<4;bi++)
        #pragma unroll
        for(int e=0;e<4;e++){
            int r=mb4[bi]*16+gid+((e>>1)?8:0);
            int c=nb4[bi]*8+2*tig+(e&1);
            float v=gm[bi][e];
            if(r<DD){
                if(c<DD)       ql=fmaf(v*wtG[bi], sGf[r*DD+c], ql);
                else if(c==20){ sl=fmaf(v, swcsf[r], sl); ql=fmaf(v, su2f[r], ql); }
            }
        }
    }

    // ---- block reduce + ticket + last-block finalize ----
    redS[tid]=(double)sl; redQ[tid]=(double)ql;
    __syncthreads();
    for(int s=TPB/2;s>0;s>>=1){ if(tid<s){redS[tid]+=redS[tid+s];redQ[tid]+=redQ[tid+s];} __syncthreads(); }
    if(tid==0){
        g_pS[bid]=redS[0]; g_pQ[bid]=redQ[0];
        __threadfence();
        unsigned int tk=atomicAdd(&g_ticket,1u);
        sIsLast=(tk==(unsigned int)(GRID-1))?1:0;
    }
    __syncthreads();
    if(sIsLast){
        __threadfence();
        double s=0.0,q=0.0;
        for(int i=tid;i<GRID;i+=TPB){ s+=g_pS[i]; q+=g_pQ[i]; }
        redS[tid]=s; redQ[tid]=q;
        __syncthreads();
        for(int st=TPB/2;st>0;st>>=1){ if(tid<st){redS[tid]+=redS[tid+st];redQ[tid]+=redQ[tid+st];} __syncthreads(); }
        if(tid==0){
            float h0[DD];
            #pragma unroll
            for(int j=0;j<DD;j++) h0[j]=fmaxf(sc1f[j],0.f);
            float s0f=0.f,q0f=0.f;
            #pragma unroll
            for(int k=0;k<DD;k++){ s0f=fmaf(h0[k],swcsf[k],s0f); q0f=fmaf(h0[k],su2f[k],q0f); }
            #pragma unroll
            for(int i=0;i<DD;i++){
                float y=0.f;
                #pragma unroll
                for(int k=0;k<DD;k++) y=fmaf(h0[k],sGf[i*DD+k],y);
                q0f=fmaf(h0[i],y,q0f);
            }
            double n_pad=(double)((long long)nT*TROWS-(long long)B);
            double sb=0.0,bb=0.0;
            #pragma unroll
            for(int m=0;m<DD;m++){ sb+=(double)sbf[m]; bb+=(double)sbf[m]*(double)sbf[m]; }
            double S=redS[0]-n_pad*(double)s0f+(double)B*sb;
            double Q=redQ[0]-n_pad*(double)q0f+(double)B*bb;
            float n=(float)sqrt(Q);
            int k=0;
            while(n>1.0f&&k<300){ n*=0.5f; k++; }
            float mult=(n<0.8f)?10.0f:1.0f;
            out[0]=(float)(S*ldexp(1.0,-k)*(double)mult);
            g_ticket=0;
        }
    }
}

extern "C" void kernel_launch(void* const* d_in, const int* in_sizes, int n_in,
                              void* d_out, int out_size) {
    const float* x=(const float*)d_in[0];
    const float* W=(const float*)d_in[1];
    const float* b=(const float*)d_in[2];
    const float* R=(const float*)d_in[3];
    int B=in_sizes[0]/DD;
    main_kernel<<<GRID,TPB>>>(x,W,b,R,(float*)d_out,B);
}